// round 3
// baseline (speedup 1.0000x reference)
#include <cuda_runtime.h>
#include <cuda_bf16.h>
#include <stdint.h>

#define NB 1024
#define NP 16
#define NE 3
#define NH 256
#define NL 4
#define NPAIR (NB*NP*NP)     // 262144
#define NBROWS (NB*NP)       // 16384

// -------------------- device scratch (no runtime allocation allowed) -----
__device__ __nv_bfloat16 g_W1t[6][256][256];   // [net][n][k]  (W1 transposed)
__device__ __nv_bfloat16 g_W2t[6][16][256];    // [net][n(pad16)][k]
__device__ float g_S[4][NPAIR][9];             // S tensors per layer
__device__ float g_bq[NBROWS][3];
__device__ float g_bp[NBROWS][3];

// -------------------- helpers --------------------------------------------
__device__ __forceinline__ float tanh_f32(float x) {
    float y; asm("tanh.approx.f32 %0, %1;" : "=f"(y) : "f"(x)); return y;
}
__device__ __forceinline__ uint32_t pack_bf16x2(float lo, float hi) {
    uint32_t r; asm("cvt.rn.bf16x2.f32 %0, %1, %2;" : "=r"(r) : "f"(hi), "f"(lo));
    return r;   // lo in lower 16 bits
}
__device__ __forceinline__ void ldsm4(uint32_t r[4], uint32_t addr) {
    asm volatile("ldmatrix.sync.aligned.m8n8.x4.shared.b16 {%0,%1,%2,%3}, [%4];"
        : "=r"(r[0]), "=r"(r[1]), "=r"(r[2]), "=r"(r[3]) : "r"(addr));
}
__device__ __forceinline__ void mma16816(float c[4],
    uint32_t a0, uint32_t a1, uint32_t a2, uint32_t a3,
    uint32_t b0, uint32_t b1) {
    asm volatile(
        "mma.sync.aligned.m16n8k16.row.col.f32.bf16.bf16.f32 "
        "{%0,%1,%2,%3},{%4,%5,%6,%7},{%8,%9},{%0,%1,%2,%3};"
        : "+f"(c[0]), "+f"(c[1]), "+f"(c[2]), "+f"(c[3])
        : "r"(a0), "r"(a1), "r"(a2), "r"(a3), "r"(b0), "r"(b1));
}

// -------------------- weight prep kernel ---------------------------------
__global__ void prep_kernel(const float* __restrict__ sW1,
                            const float* __restrict__ qW1,
                            const float* __restrict__ kW1,
                            const float* __restrict__ sW2,
                            const float* __restrict__ qW2,
                            const float* __restrict__ kW2) {
    int idx = blockIdx.x * blockDim.x + threadIdx.x;
    const int W1TOT = 6 * 256 * 256;
    if (idx < W1TOT) {
        int net = idx >> 16; int rem = idx & 65535;
        int n = rem >> 8; int k = rem & 255;
        const float* src = (net < 4) ? (sW1 + net * 65536)
                                     : ((net == 4) ? qW1 : kW1);
        g_W1t[net][n][k] = __float2bfloat16(src[k * 256 + n]);
    } else {
        int j = idx - W1TOT;
        if (j < 6 * 16 * 256) {
            int net = j / 4096; int rem = j & 4095;
            int n = rem >> 8; int k = rem & 255;
            float v = 0.f;
            if (net < 4)      { if (n < 9) v = sW2[net * 2304 + k * 9 + n]; }
            else if (net == 4){ if (n < 3) v = qW2[k * 3 + n]; }
            else              { if (n < 3) v = kW2[k * 3 + n]; }
            g_W2t[net][n][k] = __float2bfloat16(v);
        }
    }
}

// -------------------- fused MLP kernel ------------------------------------
// 256 threads = 8 warps. warp = nw*2 + mw. BM=64 rows/tile.
// GEMM1: H1[64,256] = tanh(h0[64,256] @ W1[256,256] + b1)   (bf16 HMMA)
// GEMM2: out[64,16] = tanh(H1 @ W2t^T + b2)  (A-frags direct from GEMM1 C-frags)
struct SmemLayout {
    __nv_bfloat16 W1t[256][264];   // [n][k] padded
    __nv_bfloat16 h0[64][264];     // [row][k] padded
    __nv_bfloat16 W2t[16][264];    // [n][k] padded
    float red[8][32][16];          // GEMM2 partials per warp
    float b1s[256];
    float b0s[256];
    float W0s[2][256];
    float b2s[16];
    float mjs[64];
    float mis[64];
};

__global__ void __launch_bounds__(256, 1) mlp_fused(
    const float* __restrict__ m,
    const float* __restrict__ W0_0, const float* __restrict__ b0_0,
    const float* __restrict__ b1_0, const float* __restrict__ b2_0,
    const float* __restrict__ W0_1, const float* __restrict__ b0_1,
    const float* __restrict__ b1_1, const float* __restrict__ b2_1,
    int net_base, int pair_mode, int ntiles, int out_valid)
{
    extern __shared__ char smem_raw[];
    SmemLayout& S = *reinterpret_cast<SmemLayout*>(smem_raw);
    const int t = threadIdx.x;
    const int warp = t >> 5, lane = t & 31;
    const int g = lane >> 2, tg = lane & 3;
    const int mw = warp & 1, nw = warp >> 1;
    const int y = blockIdx.y;
    const int net = net_base + y;

    const float *W0g, *b0g, *b1g, *b2g;
    float* op;
    if (pair_mode) {
        W0g = W0_0 + y * 2 * NH; b0g = b0_0 + y * NH;
        b1g = b1_0 + y * NH;     b2g = b2_0 + y * 9;
        op  = &g_S[y][0][0];
    } else {
        if (y == 0) { W0g = W0_0; b0g = b0_0; b1g = b1_0; b2g = b2_0; op = &g_bq[0][0]; }
        else        { W0g = W0_1; b0g = b0_1; b1g = b1_1; b2g = b2_1; op = &g_bp[0][0]; }
    }

    // ---- load weights to smem (once per block) ----
    {
        const uint4* src = reinterpret_cast<const uint4*>(&g_W1t[net][0][0]);
        for (int idx = t; idx < 256 * 32; idx += 256) {
            int n = idx >> 5, ch = idx & 31;
            *reinterpret_cast<uint4*>(&S.W1t[n][ch * 8]) = src[idx];
        }
        const uint4* src2 = reinterpret_cast<const uint4*>(&g_W2t[net][0][0]);
        for (int idx = t; idx < 16 * 32; idx += 256) {
            int n = idx >> 5, ch = idx & 31;
            *reinterpret_cast<uint4*>(&S.W2t[n][ch * 8]) = src2[idx];
        }
        S.b1s[t] = b1g[t];
        S.b0s[t] = b0g[t];
        S.W0s[0][t] = W0g[t];
        S.W0s[1][t] = pair_mode ? W0g[NH + t] : 0.f;
        if (t < 16) S.b2s[t] = (t < out_valid) ? b2g[t] : 0.f;
    }
    __syncthreads();

    const int a_r = (lane & 7) + ((lane & 8) ? 8 : 0);
    const int a_c = (lane & 16) ? 8 : 0;
    const uint32_t h0base = (uint32_t)__cvta_generic_to_shared(&S.h0[0][0]);

    for (int tile = blockIdx.x; tile < ntiles; tile += gridDim.x) {
        const int row0 = tile * 64;
        // ---- m values for this tile ----
        if (t < 64) {
            int rg = row0 + t;
            float xj, xi;
            if (pair_mode) {
                int b = rg >> 8, ij = rg & 255;
                int i = ij >> 4, j = ij & 15;
                xj = m[b * NP + j]; xi = m[b * NP + i];
            } else { xj = m[rg]; xi = 0.f; }
            S.mjs[t] = xj; S.mis[t] = xi;
        }
        __syncthreads();

        // ---- h0 = tanh(x @ W0 + b0) into smem (bf16) ----
        {
            int r = t >> 2, cb = (t & 3) * 64;
            float xj = S.mjs[r], xi = S.mis[r];
            #pragma unroll
            for (int k = 0; k < 64; k += 2) {
                int kk = cb + k;
                float a0 = fmaf(xj, S.W0s[0][kk],   fmaf(xi, S.W0s[1][kk],   S.b0s[kk]));
                float a1 = fmaf(xj, S.W0s[0][kk+1], fmaf(xi, S.W0s[1][kk+1], S.b0s[kk+1]));
                *reinterpret_cast<uint32_t*>(&S.h0[r][kk]) =
                    pack_bf16x2(tanh_f32(a0), tanh_f32(a1));
            }
        }
        __syncthreads();

        // ---- GEMM1: acc = h0 @ W1 (this warp: rows mw*32..+31, cols nw*64..+63)
        float acc[2][8][4];
        #pragma unroll
        for (int mt = 0; mt < 2; mt++)
            #pragma unroll
            for (int nt = 0; nt < 8; nt++)
                #pragma unroll
                for (int c = 0; c < 4; c++) acc[mt][nt][c] = 0.f;

        const int rbase = mw * 32;
        #pragma unroll 4
        for (int kt = 0; kt < 16; kt++) {
            uint32_t a[2][4];
            #pragma unroll
            for (int mt = 0; mt < 2; mt++) {
                uint32_t addr = h0base +
                    (uint32_t)(((rbase + mt * 16 + a_r) * 264 + kt * 16 + a_c) * 2);
                ldsm4(a[mt], addr);
            }
            #pragma unroll
            for (int nt = 0; nt < 8; nt++) {
                int n = nw * 64 + nt * 8 + g;
                uint32_t b0 = *reinterpret_cast<const uint32_t*>(&S.W1t[n][kt * 16 + 2 * tg]);
                uint32_t b1 = *reinterpret_cast<const uint32_t*>(&S.W1t[n][kt * 16 + 2 * tg + 8]);
                mma16816(acc[0][nt], a[0][0], a[0][1], a[0][2], a[0][3], b0, b1);
                mma16816(acc[1][nt], a[1][0], a[1][1], a[1][2], a[1][3], b0, b1);
            }
        }

        // ---- epilogue1: +b1, tanh, pack directly into GEMM2 A-fragments ----
        uint32_t A2[2][8][2];
        #pragma unroll
        for (int nt = 0; nt < 8; nt++) {
            int c0 = nw * 64 + nt * 8 + 2 * tg;
            float bb0 = S.b1s[c0], bb1 = S.b1s[c0 + 1];
            #pragma unroll
            for (int mt = 0; mt < 2; mt++) {
                float v0 = tanh_f32(acc[mt][nt][0] + bb0);
                float v1 = tanh_f32(acc[mt][nt][1] + bb1);
                float v2 = tanh_f32(acc[mt][nt][2] + bb0);
                float v3 = tanh_f32(acc[mt][nt][3] + bb1);
                A2[mt][nt][0] = pack_bf16x2(v0, v1);
                A2[mt][nt][1] = pack_bf16x2(v2, v3);
            }
        }

        // ---- GEMM2 (per-warp k-slice nw*64..+63, partial sums) ----
        float c2[2][2][4];
        #pragma unroll
        for (int mt = 0; mt < 2; mt++)
            #pragma unroll
            for (int nb = 0; nb < 2; nb++)
                #pragma unroll
                for (int c = 0; c < 4; c++) c2[mt][nb][c] = 0.f;

        #pragma unroll
        for (int kt2 = 0; kt2 < 4; kt2++) {
            #pragma unroll
            for (int mt = 0; mt < 2; mt++) {
                uint32_t a0 = A2[mt][2 * kt2][0],     a1 = A2[mt][2 * kt2][1];
                uint32_t a2 = A2[mt][2 * kt2 + 1][0], a3 = A2[mt][2 * kt2 + 1][1];
                #pragma unroll
                for (int nb = 0; nb < 2; nb++) {
                    uint32_t b0 = *reinterpret_cast<const uint32_t*>(
                        &S.W2t[nb * 8 + g][nw * 64 + kt2 * 16 + 2 * tg]);
                    uint32_t b1 = *reinterpret_cast<const uint32_t*>(
                        &S.W2t[nb * 8 + g][nw * 64 + kt2 * 16 + 2 * tg + 8]);
                    mma16816(c2[mt][nb], a0, a1, a2, a3, b0, b1);
                }
            }
        }

        // ---- stage partials ----
        #pragma unroll
        for (int mt = 0; mt < 2; mt++)
            #pragma unroll
            for (int nb = 0; nb < 2; nb++)
                #pragma unroll
                for (int c = 0; c < 4; c++) {
                    int rr = mt * 16 + g + ((c >> 1) & 1) * 8;
                    int cc = nb * 8 + 2 * tg + (c & 1);
                    S.red[warp][rr][cc] = c2[mt][nb][c];
                }
        __syncthreads();

        // ---- reduce over 4 k-slices, +b2, tanh, store ----
        {
            int r64 = t >> 2, cq = t & 3;
            int mw2 = r64 >> 5, r32 = r64 & 31;
            #pragma unroll
            for (int cc = 0; cc < 4; cc++) {
                int col = cq * 4 + cc;
                float s = S.b2s[col];
                #pragma unroll
                for (int nn = 0; nn < 4; nn++) s += S.red[nn * 2 + mw2][r32][col];
                s = tanh_f32(s);
                if (col < out_valid)
                    op[(size_t)(row0 + r64) * out_valid + col] = s;
            }
        }
        __syncthreads();
    }
}

// -------------------- final assembly: sequential symplectic updates -------
__global__ void __launch_bounds__(256) assemble_kernel(
    const float* __restrict__ q, const float* __restrict__ p,
    const float* __restrict__ dtp, float* __restrict__ out)
{
    __shared__ float qf[48], pf[48];
    __shared__ float Sc[256][9];
    int b = blockIdx.x, t = threadIdx.x;
    if (t < 48) { qf[t] = q[b * 48 + t]; pf[t] = p[b * 48 + t]; }
    float dt = dtp[0];
    float scale = dt * dt * dt;
    __syncthreads();

    #pragma unroll
    for (int l = 0; l < 4; l++) {
        #pragma unroll
        for (int c = 0; c < 9; c++) Sc[t][c] = g_S[l][b * 256 + t][c];
        __syncthreads();
        const float* src = (l & 1) ? pf : qf;
        float*       dst = (l & 1) ? qf : pf;
        if (t < 48) {
            int i = t / 3, a = t - (t / 3) * 3;
            float s = 0.f;
            // M part: M[(i,a),(j,c)] = S[b,i,j,a,c]
            #pragma unroll
            for (int j = 0; j < 16; j++)
                #pragma unroll
                for (int c = 0; c < 3; c++)
                    s += Sc[i * 16 + j][a * 3 + c] * src[j * 3 + c];
            // M^T part: (M^T)[(i,a),(j,c)] = S[b,j,i,c,a]
            #pragma unroll
            for (int ii = 0; ii < 16; ii++)
                #pragma unroll
                for (int aa = 0; aa < 3; aa++)
                    s += Sc[ii * 16 + i][aa * 3 + a] * src[ii * 3 + aa];
            dst[t] += s * scale;
        }
        __syncthreads();
    }

    if (t < 48) {
        int row = b * 16 + t / 3, e = t - (t / 3) * 3;
        out[b * 48 + t]           = qf[t] + g_bq[row][e] * scale;
        out[NB * 48 + b * 48 + t] = pf[t] + g_bp[row][e] * scale;
    }
}

// -------------------- launch ----------------------------------------------
extern "C" void kernel_launch(void* const* d_in, const int* in_sizes, int n_in,
                              void* d_out, int out_size) {
    const float* q   = (const float*)d_in[0];
    const float* p   = (const float*)d_in[1];
    const float* m   = (const float*)d_in[2];
    const float* dt  = (const float*)d_in[3];
    const float* sW0 = (const float*)d_in[4];
    const float* sb0 = (const float*)d_in[5];
    const float* sW1 = (const float*)d_in[6];
    const float* sb1 = (const float*)d_in[7];
    const float* sW2 = (const float*)d_in[8];
    const float* sb2 = (const float*)d_in[9];
    const float* qW0 = (const float*)d_in[10];
    const float* qb0 = (const float*)d_in[11];
    const float* qW1 = (const float*)d_in[12];
    const float* qb1 = (const float*)d_in[13];
    const float* qW2 = (const float*)d_in[14];
    const float* qb2 = (const float*)d_in[15];
    const float* kW0 = (const float*)d_in[16];
    const float* kb0 = (const float*)d_in[17];
    const float* kW1 = (const float*)d_in[18];
    const float* kb1 = (const float*)d_in[19];
    const float* kW2 = (const float*)d_in[20];
    const float* kb2 = (const float*)d_in[21];
    float* out = (float*)d_out;

    static bool attr_set = false;
    if (!attr_set) {
        cudaFuncSetAttribute(mlp_fused, cudaFuncAttributeMaxDynamicSharedMemorySize,
                             (int)sizeof(SmemLayout));
        attr_set = true;
    }

    // 1) weight prep (fp32 -> bf16, transposed)
    {
        int total = 6 * 256 * 256 + 6 * 16 * 256;
        prep_kernel<<<(total + 255) / 256, 256>>>(sW1, qW1, kW1, sW2, qW2, kW2);
    }
    // 2) pair MLPs: all 4 S layers in parallel (grid.y = layer)
    {
        dim3 grid(37, 4);
        mlp_fused<<<grid, 256, sizeof(SmemLayout)>>>(
            m, sW0, sb0, sb1, sb2,
            nullptr, nullptr, nullptr, nullptr,
            0, 1, NPAIR / 64, 9);
    }
    // 3) bias MLPs (q-net, k-net)
    {
        dim3 grid(74, 2);
        mlp_fused<<<grid, 256, sizeof(SmemLayout)>>>(
            m, qW0, qb0, qb1, qb2,
            kW0, kb0, kb1, kb2,
            4, 0, NBROWS / 64, 3);
    }
    // 4) assemble sequential symplectic updates + biases -> output
    assemble_kernel<<<NB, 256>>>(q, p, dt, out);
}

// round 5
// speedup vs baseline: 15.7933x; 15.7933x over previous
#include <cuda_runtime.h>
#include <cuda_bf16.h>
#include <stdint.h>

#define NB 1024
#define NP 16
#define NH 256
// S-grid: 41x41 nodes over [0,1]^2, rows padded to 27*64=1728
#define GN 41
#define GC 40
#define SG_ROWS 1728
#define SG_TILES 27
// bias grid: 1025 nodes over [0,1], padded to 17*64=1088
#define BG_ROWS 1088
#define BG_TILES 17

__device__ __nv_bfloat16 g_W1t[6][256][256];   // [net][n][k]
__device__ __nv_bfloat16 g_W2t[6][16][256];
__device__ float g_Sgrid[4][SG_ROWS][12];      // S MLP on grid, stride 12
__device__ float g_Bgrid[2][BG_ROWS][4];       // bias MLPs on 1-D grid, stride 4

__device__ __forceinline__ float tanh_f32(float x) {
    float y; asm("tanh.approx.f32 %0, %1;" : "=f"(y) : "f"(x)); return y;
}
__device__ __forceinline__ uint32_t pack_bf16x2(float lo, float hi) {
    uint32_t r; asm("cvt.rn.bf16x2.f32 %0, %1, %2;" : "=r"(r) : "f"(hi), "f"(lo));
    return r;
}
__device__ __forceinline__ void ldsm4(uint32_t r[4], uint32_t addr) {
    asm volatile("ldmatrix.sync.aligned.m8n8.x4.shared.b16 {%0,%1,%2,%3}, [%4];"
        : "=r"(r[0]), "=r"(r[1]), "=r"(r[2]), "=r"(r[3]) : "r"(addr));
}
__device__ __forceinline__ void mma16816(float c[4],
    uint32_t a0, uint32_t a1, uint32_t a2, uint32_t a3,
    uint32_t b0, uint32_t b1) {
    asm volatile(
        "mma.sync.aligned.m16n8k16.row.col.f32.bf16.bf16.f32 "
        "{%0,%1,%2,%3},{%4,%5,%6,%7},{%8,%9},{%0,%1,%2,%3};"
        : "+f"(c[0]), "+f"(c[1]), "+f"(c[2]), "+f"(c[3])
        : "r"(a0), "r"(a1), "r"(a2), "r"(a3), "r"(b0), "r"(b1));
}

// -------------------- weight prep (proven) --------------------------------
__global__ void prep_kernel(const float* __restrict__ sW1, const float* __restrict__ qW1,
                            const float* __restrict__ kW1, const float* __restrict__ sW2,
                            const float* __restrict__ qW2, const float* __restrict__ kW2) {
    int idx = blockIdx.x * blockDim.x + threadIdx.x;
    const int W1TOT = 6 * 65536;
    if (idx < W1TOT) {
        int net = idx >> 16, rem = idx & 65535, n = rem >> 8, k = rem & 255;
        const float* src = (net < 4) ? (sW1 + net * 65536) : ((net == 4) ? qW1 : kW1);
        g_W1t[net][n][k] = __float2bfloat16(src[k * 256 + n]);
    } else {
        int j = idx - W1TOT;
        if (j < 6 * 4096) {
            int net = j >> 12, rem = j & 4095, n = rem >> 8, k = rem & 255;
            float v = 0.f;
            if (net < 4)       { if (n < 9) v = sW2[net * 2304 + k * 9 + n]; }
            else if (net == 4) { if (n < 3) v = qW2[k * 3 + n]; }
            else               { if (n < 3) v = kW2[k * 3 + n]; }
            g_W2t[net][n][k] = __float2bfloat16(v);
        }
    }
}

// -------------------- MLP grid-evaluation kernel (proven core) -------------
struct SmemLayout {
    __nv_bfloat16 W1t[256][264];
    __nv_bfloat16 h0[64][264];
    __nv_bfloat16 W2t[16][264];
    float red[8][32][16];
    float b1s[256];
    float b0s[256];
    float W0s[2][256];
    float b2s[16];
    float mjs[64];
    float mis[64];
};

__global__ void __launch_bounds__(256, 1) mlp_grid(
    const float* __restrict__ sW0, const float* __restrict__ sb0,
    const float* __restrict__ sb1, const float* __restrict__ sb2,
    const float* __restrict__ qW0, const float* __restrict__ qb0,
    const float* __restrict__ qb1, const float* __restrict__ qb2,
    const float* __restrict__ kW0, const float* __restrict__ kb0,
    const float* __restrict__ kb1, const float* __restrict__ kb2)
{
    extern __shared__ char smem_raw[];
    SmemLayout& S = *reinterpret_cast<SmemLayout*>(smem_raw);
    const int t = threadIdx.x;
    const int warp = t >> 5, lane = t & 31;
    const int g = lane >> 2, tg = lane & 3;
    const int mw = warp & 1, nw = warp >> 1;
    const int y = blockIdx.y;
    const int sgrid_mode = (y < 4);
    const int ntiles = sgrid_mode ? SG_TILES : BG_TILES;
    if ((int)blockIdx.x >= ntiles) return;
    const int net = y;
    const int out_valid = sgrid_mode ? 9 : 3;
    const int ostride = sgrid_mode ? 12 : 4;

    const float *W0g, *b0g, *b1g, *b2g; float* op;
    if (y < 4) { W0g = sW0 + y*512; b0g = sb0 + y*256; b1g = sb1 + y*256;
                 b2g = sb2 + y*9; op = &g_Sgrid[y][0][0]; }
    else if (y == 4) { W0g = qW0; b0g = qb0; b1g = qb1; b2g = qb2; op = &g_Bgrid[0][0][0]; }
    else { W0g = kW0; b0g = kb0; b1g = kb1; b2g = kb2; op = &g_Bgrid[1][0][0]; }

    {
        const uint4* src = reinterpret_cast<const uint4*>(&g_W1t[net][0][0]);
        for (int idx = t; idx < 8192; idx += 256) {
            int n = idx >> 5, ch = idx & 31;
            *reinterpret_cast<uint4*>(&S.W1t[n][ch * 8]) = src[idx];
        }
        const uint4* src2 = reinterpret_cast<const uint4*>(&g_W2t[net][0][0]);
        for (int idx = t; idx < 512; idx += 256) {
            int n = idx >> 5, ch = idx & 31;
            *reinterpret_cast<uint4*>(&S.W2t[n][ch * 8]) = src2[idx];
        }
        S.b1s[t] = b1g[t];
        S.b0s[t] = b0g[t];
        S.W0s[0][t] = W0g[t];
        S.W0s[1][t] = sgrid_mode ? W0g[NH + t] : 0.f;
        if (t < 16) S.b2s[t] = (t < out_valid) ? b2g[t] : 0.f;
    }
    __syncthreads();

    const int a_r = (lane & 7) + ((lane & 8) ? 8 : 0);
    const int a_c = (lane & 16) ? 8 : 0;
    const uint32_t h0base = (uint32_t)__cvta_generic_to_shared(&S.h0[0][0]);

    for (int tile = blockIdx.x; tile < ntiles; tile += gridDim.x) {
        const int row0 = tile * 64;
        if (t < 64) {
            int rg = row0 + t;
            float xj, xi;
            if (sgrid_mode) {
                int gA = rg / GN;
                xj = (float)gA * (1.f / (float)GC);
                xi = (float)(rg - gA * GN) * (1.f / (float)GC);
            } else { xj = (float)rg * (1.f / 1024.f); xi = 0.f; }
            S.mjs[t] = xj; S.mis[t] = xi;
        }
        __syncthreads();

        {
            int r = t >> 2, cb = (t & 3) * 64;
            float xj = S.mjs[r], xi = S.mis[r];
            #pragma unroll
            for (int k = 0; k < 64; k += 2) {
                int kk = cb + k;
                float a0 = fmaf(xj, S.W0s[0][kk],   fmaf(xi, S.W0s[1][kk],   S.b0s[kk]));
                float a1 = fmaf(xj, S.W0s[0][kk+1], fmaf(xi, S.W0s[1][kk+1], S.b0s[kk+1]));
                *reinterpret_cast<uint32_t*>(&S.h0[r][kk]) =
                    pack_bf16x2(tanh_f32(a0), tanh_f32(a1));
            }
        }
        __syncthreads();

        float acc[2][8][4];
        #pragma unroll
        for (int mt = 0; mt < 2; mt++)
            #pragma unroll
            for (int nt = 0; nt < 8; nt++)
                #pragma unroll
                for (int c = 0; c < 4; c++) acc[mt][nt][c] = 0.f;

        const int rbase = mw * 32;
        #pragma unroll 4
        for (int kt = 0; kt < 16; kt++) {
            uint32_t a[2][4];
            #pragma unroll
            for (int mt = 0; mt < 2; mt++) {
                uint32_t addr = h0base +
                    (uint32_t)(((rbase + mt * 16 + a_r) * 264 + kt * 16 + a_c) * 2);
                ldsm4(a[mt], addr);
            }
            #pragma unroll
            for (int nt = 0; nt < 8; nt++) {
                int n = nw * 64 + nt * 8 + g;
                uint32_t b0 = *reinterpret_cast<const uint32_t*>(&S.W1t[n][kt * 16 + 2 * tg]);
                uint32_t b1 = *reinterpret_cast<const uint32_t*>(&S.W1t[n][kt * 16 + 2 * tg + 8]);
                mma16816(acc[0][nt], a[0][0], a[0][1], a[0][2], a[0][3], b0, b1);
                mma16816(acc[1][nt], a[1][0], a[1][1], a[1][2], a[1][3], b0, b1);
            }
        }

        uint32_t A2[2][8][2];
        #pragma unroll
        for (int nt = 0; nt < 8; nt++) {
            int c0 = nw * 64 + nt * 8 + 2 * tg;
            float bb0 = S.b1s[c0], bb1 = S.b1s[c0 + 1];
            #pragma unroll
            for (int mt = 0; mt < 2; mt++) {
                float v0 = tanh_f32(acc[mt][nt][0] + bb0);
                float v1 = tanh_f32(acc[mt][nt][1] + bb1);
                float v2 = tanh_f32(acc[mt][nt][2] + bb0);
                float v3 = tanh_f32(acc[mt][nt][3] + bb1);
                A2[mt][nt][0] = pack_bf16x2(v0, v1);
                A2[mt][nt][1] = pack_bf16x2(v2, v3);
            }
        }

        float c2[2][2][4];
        #pragma unroll
        for (int mt = 0; mt < 2; mt++)
            #pragma unroll
            for (int nb = 0; nb < 2; nb++)
                #pragma unroll
                for (int c = 0; c < 4; c++) c2[mt][nb][c] = 0.f;

        #pragma unroll
        for (int kt2 = 0; kt2 < 4; kt2++) {
            #pragma unroll
            for (int mt = 0; mt < 2; mt++) {
                uint32_t a0 = A2[mt][2 * kt2][0],     a1 = A2[mt][2 * kt2][1];
                uint32_t a2 = A2[mt][2 * kt2 + 1][0], a3 = A2[mt][2 * kt2 + 1][1];
                #pragma unroll
                for (int nb = 0; nb < 2; nb++) {
                    uint32_t b0 = *reinterpret_cast<const uint32_t*>(
                        &S.W2t[nb * 8 + g][nw * 64 + kt2 * 16 + 2 * tg]);
                    uint32_t b1 = *reinterpret_cast<const uint32_t*>(
                        &S.W2t[nb * 8 + g][nw * 64 + kt2 * 16 + 2 * tg + 8]);
                    mma16816(c2[mt][nb], a0, a1, a2, a3, b0, b1);
                }
            }
        }

        #pragma unroll
        for (int mt = 0; mt < 2; mt++)
            #pragma unroll
            for (int nb = 0; nb < 2; nb++)
                #pragma unroll
                for (int c = 0; c < 4; c++) {
                    int rr = mt * 16 + g + ((c >> 1) & 1) * 8;
                    int cc = nb * 8 + 2 * tg + (c & 1);
                    S.red[warp][rr][cc] = c2[mt][nb][c];
                }
        __syncthreads();

        {
            int r64 = t >> 2, cq = t & 3;
            int mw2 = r64 >> 5, r32 = r64 & 31;
            #pragma unroll
            for (int cc = 0; cc < 4; cc++) {
                int col = cq * 4 + cc;
                float s = S.b2s[col];
                #pragma unroll
                for (int nn = 0; nn < 4; nn++) s += S.red[nn * 2 + mw2][r32][col];
                s = tanh_f32(s);
                if (col < out_valid)
                    op[(size_t)(row0 + r64) * ostride + col] = s;
            }
        }
        __syncthreads();
    }
}

// -------------------- assemble: interp + symplectic updates ---------------
__device__ __forceinline__ void bilerp9(const float* __restrict__ Gl,
    int cu, int cv, float fu, float fv, float* A)
{
    const float4* r00 = (const float4*)(Gl + (size_t)(cu * GN + cv) * 12);
    const float4* r01 = (const float4*)(Gl + (size_t)(cu * GN + cv + 1) * 12);
    const float4* r10 = (const float4*)(Gl + (size_t)((cu + 1) * GN + cv) * 12);
    const float4* r11 = (const float4*)(Gl + (size_t)((cu + 1) * GN + cv + 1) * 12);
    #pragma unroll
    for (int w = 0; w < 3; w++) {
        float4 a = __ldg(&r00[w]), b = __ldg(&r01[w]);
        float4 c = __ldg(&r10[w]), d = __ldg(&r11[w]);
        float e0x = a.x + fv * (b.x - a.x), e1x = c.x + fv * (d.x - c.x);
        float e0y = a.y + fv * (b.y - a.y), e1y = c.y + fv * (d.y - c.y);
        float e0z = a.z + fv * (b.z - a.z), e1z = c.z + fv * (d.z - c.z);
        float e0w = a.w + fv * (b.w - a.w), e1w = c.w + fv * (d.w - c.w);
        A[w * 4 + 0] = e0x + fu * (e1x - e0x);
        A[w * 4 + 1] = e0y + fu * (e1y - e0y);
        A[w * 4 + 2] = e0z + fu * (e1z - e0z);
        A[w * 4 + 3] = e0w + fu * (e1w - e0w);
    }
}

__global__ void __launch_bounds__(256) assemble_interp(
    const float* __restrict__ q, const float* __restrict__ p,
    const float* __restrict__ m, const float* __restrict__ dtp,
    float* __restrict__ out)
{
    __shared__ float qf[48], pf[48];
    __shared__ float fr[16]; __shared__ int cl[16];
    __shared__ float frB[16]; __shared__ int clB[16];
    const int b = blockIdx.x, t = threadIdx.x;
    if (t < 48) { qf[t] = q[b * 48 + t]; pf[t] = p[b * 48 + t]; }
    if (t < 16) {
        float mv = m[b * 16 + t];
        float u = mv * (float)GC; int c = (int)u; if (c > GC - 1) c = GC - 1;
        cl[t] = c; fr[t] = u - (float)c;
        float uB = mv * 1024.f; int cB = (int)uB; if (cB > 1023) cB = 1023;
        clB[t] = cB; frB[t] = uB - (float)cB;
    }
    float dt = dtp[0];
    const float scale = dt * dt * dt;
    __syncthreads();

    const int i = t >> 4, j = t & 15;
    const int cu1 = cl[j], cv1 = cl[i];   // S(i,j) = MLP(m[j], m[i])
    const float fu1 = fr[j], fv1 = fr[i];
    const int cu2 = cl[i], cv2 = cl[j];   // S(j,i) = MLP(m[i], m[j])
    const float fu2 = fr[i], fv2 = fr[j];

    #pragma unroll
    for (int l = 0; l < 4; l++) {
        const float* Gl = &g_Sgrid[l][0][0];
        float A1[12], A2[12];
        bilerp9(Gl, cu1, cv1, fu1, fv1, A1);
        bilerp9(Gl, cu2, cv2, fu2, fv2, A2);
        const float* src = (l & 1) ? pf : qf;
        float*       dst = (l & 1) ? qf : pf;
        float sj0 = src[j * 3 + 0], sj1 = src[j * 3 + 1], sj2 = src[j * 3 + 2];
        float y0 = A1[0]*sj0 + A1[1]*sj1 + A1[2]*sj2
                 + A2[0]*sj0 + A2[3]*sj1 + A2[6]*sj2;
        float y1 = A1[3]*sj0 + A1[4]*sj1 + A1[5]*sj2
                 + A2[1]*sj0 + A2[4]*sj1 + A2[7]*sj2;
        float y2 = A1[6]*sj0 + A1[7]*sj1 + A1[8]*sj2
                 + A2[2]*sj0 + A2[5]*sj1 + A2[8]*sj2;
        #pragma unroll
        for (int off = 8; off; off >>= 1) {
            y0 += __shfl_xor_sync(0xffffffffu, y0, off);
            y1 += __shfl_xor_sync(0xffffffffu, y1, off);
            y2 += __shfl_xor_sync(0xffffffffu, y2, off);
        }
        if (j == 0) {
            dst[i * 3 + 0] += scale * y0;
            dst[i * 3 + 1] += scale * y1;
            dst[i * 3 + 2] += scale * y2;
        }
        __syncthreads();
    }

    if (t < 48) {
        int pi = t / 3, e = t - pi * 3;
        int c = clB[pi]; float f = frB[pi];
        float bq0 = g_Bgrid[0][c][e], bq1 = g_Bgrid[0][c + 1][e];
        float bp0 = g_Bgrid[1][c][e], bp1 = g_Bgrid[1][c + 1][e];
        out[b * 48 + t]           = qf[t] + (bq0 + f * (bq1 - bq0)) * scale;
        out[NB * 48 + b * 48 + t] = pf[t] + (bp0 + f * (bp1 - bp0)) * scale;
    }
}

// -------------------- launch ------------------------------------------------
extern "C" void kernel_launch(void* const* d_in, const int* in_sizes, int n_in,
                              void* d_out, int out_size) {
    const float* q   = (const float*)d_in[0];
    const float* p   = (const float*)d_in[1];
    const float* m   = (const float*)d_in[2];
    const float* dt  = (const float*)d_in[3];
    const float* sW0 = (const float*)d_in[4];
    const float* sb0 = (const float*)d_in[5];
    const float* sW1 = (const float*)d_in[6];
    const float* sb1 = (const float*)d_in[7];
    const float* sW2 = (const float*)d_in[8];
    const float* sb2 = (const float*)d_in[9];
    const float* qW0 = (const float*)d_in[10];
    const float* qb0 = (const float*)d_in[11];
    const float* qW1 = (const float*)d_in[12];
    const float* qb1 = (const float*)d_in[13];
    const float* qW2 = (const float*)d_in[14];
    const float* qb2 = (const float*)d_in[15];
    const float* kW0 = (const float*)d_in[16];
    const float* kb0 = (const float*)d_in[17];
    const float* kW1 = (const float*)d_in[18];
    const float* kb1 = (const float*)d_in[19];
    const float* kW2 = (const float*)d_in[20];
    const float* kb2 = (const float*)d_in[21];
    float* out = (float*)d_out;

    static bool once = false;
    if (!once) {
        cudaFuncSetAttribute(mlp_grid, cudaFuncAttributeMaxDynamicSharedMemorySize,
                             (int)sizeof(SmemLayout));
        once = true;
    }
    prep_kernel<<<(6 * 65536 + 6 * 4096 + 255) / 256, 256>>>(sW1, qW1, kW1, sW2, qW2, kW2);
    {
        dim3 grid(SG_TILES, 6);
        mlp_grid<<<grid, 256, sizeof(SmemLayout)>>>(
            sW0, sb0, sb1, sb2, qW0, qb0, qb1, qb2, kW0, kb0, kb1, kb2);
    }
    assemble_interp<<<NB, 256>>>(q, p, m, dt, out);
}

// round 6
// speedup vs baseline: 18.8197x; 1.1916x over previous
#include <cuda_runtime.h>
#include <cuda_bf16.h>
#include <cuda_fp16.h>
#include <stdint.h>

#define NB 1024
#define NP 16
#define NH 256
// S-grid: 25x25 nodes over [0,1]^2 -> 625 rows, padded to 640 (10 tiles of 64)
#define GN 25
#define GC 24
#define SG_TILES 10
// bias grid: 257 nodes over [0,1], padded to 320 (5 tiles)
#define BGC 256
#define BG_TILES 5

__device__ __half g_SgH[4][640][16];      // S MLP on grid, fp16, 32B rows
__device__ float  g_Bgrid[2][320][4];     // bias MLPs on 1-D grid

__device__ __forceinline__ float tanh_f32(float x) {
    float y; asm("tanh.approx.f32 %0, %1;" : "=f"(y) : "f"(x)); return y;
}
__device__ __forceinline__ uint32_t pack_bf16x2(float lo, float hi) {
    uint32_t r; asm("cvt.rn.bf16x2.f32 %0, %1, %2;" : "=r"(r) : "f"(hi), "f"(lo));
    return r;
}
__device__ __forceinline__ void ldsm4(uint32_t r[4], uint32_t addr) {
    asm volatile("ldmatrix.sync.aligned.m8n8.x4.shared.b16 {%0,%1,%2,%3}, [%4];"
        : "=r"(r[0]), "=r"(r[1]), "=r"(r[2]), "=r"(r[3]) : "r"(addr));
}
__device__ __forceinline__ void mma16816(float c[4],
    uint32_t a0, uint32_t a1, uint32_t a2, uint32_t a3,
    uint32_t b0, uint32_t b1) {
    asm volatile(
        "mma.sync.aligned.m16n8k16.row.col.f32.bf16.bf16.f32 "
        "{%0,%1,%2,%3},{%4,%5,%6,%7},{%8,%9},{%0,%1,%2,%3};"
        : "+f"(c[0]), "+f"(c[1]), "+f"(c[2]), "+f"(c[3])
        : "r"(a0), "r"(a1), "r"(a2), "r"(a3), "r"(b0), "r"(b1));
}

// -------------------- MLP grid-evaluation kernel ---------------------------
struct __align__(16) SmemLayout {
    __nv_bfloat16 W1t[256][258];   // [n][k], pad 258 -> conflict-free transpose
    __nv_bfloat16 h0[64][264];     // [row][k] padded for ldsm
    __nv_bfloat16 W2t[16][258];
    float red[8][32][16];
    float b1s[256];
    float b0s[256];
    float W0s[2][256];
    float b2s[16];
    float mjs[64];
    float mis[64];
};

__global__ void __launch_bounds__(256, 1) mlp_grid(
    const float* __restrict__ sW0, const float* __restrict__ sb0,
    const float* __restrict__ sW1, const float* __restrict__ sb1,
    const float* __restrict__ sW2, const float* __restrict__ sb2,
    const float* __restrict__ qW0, const float* __restrict__ qb0,
    const float* __restrict__ qW1, const float* __restrict__ qb1,
    const float* __restrict__ qW2, const float* __restrict__ qb2,
    const float* __restrict__ kW0, const float* __restrict__ kb0,
    const float* __restrict__ kW1, const float* __restrict__ kb1,
    const float* __restrict__ kW2, const float* __restrict__ kb2)
{
    extern __shared__ char smem_raw[];
    SmemLayout& S = *reinterpret_cast<SmemLayout*>(smem_raw);
    const int t = threadIdx.x;
    const int warp = t >> 5, lane = t & 31;
    const int g = lane >> 2, tg = lane & 3;
    const int mw = warp & 1, nw = warp >> 1;
    const int y = blockIdx.y;
    const int sgrid_mode = (y < 4);
    const int ntiles = sgrid_mode ? SG_TILES : BG_TILES;
    if ((int)blockIdx.x >= ntiles) return;
    const int out_valid = sgrid_mode ? 9 : 3;

    const float *W0g, *b0g, *b1g, *b2g;
    const float* w1src;
    if (y < 4) { W0g = sW0 + y * 512; b0g = sb0 + y * 256; b1g = sb1 + y * 256;
                 b2g = sb2 + y * 9; w1src = sW1 + y * 65536; }
    else if (y == 4) { W0g = qW0; b0g = qb0; b1g = qb1; b2g = qb2; w1src = qW1; }
    else { W0g = kW0; b0g = kb0; b1g = kb1; b2g = kb2; w1src = kW1; }

    // ---- inline weight conversion: fp32 [k][n] -> bf16 smem [n][k] ----
    for (int it = 0; it < 256; it++)
        S.W1t[t][it] = __float2bfloat16(w1src[it * 256 + t]);
    {
        #pragma unroll
        for (int n = 0; n < 16; n++) {
            float v = 0.f;
            if (y < 4)       { if (n < 9) v = sW2[y * 2304 + t * 9 + n]; }
            else if (y == 4) { if (n < 3) v = qW2[t * 3 + n]; }
            else             { if (n < 3) v = kW2[t * 3 + n]; }
            S.W2t[n][t] = __float2bfloat16(v);
        }
        S.b1s[t] = b1g[t];
        S.b0s[t] = b0g[t];
        S.W0s[0][t] = W0g[t];
        S.W0s[1][t] = sgrid_mode ? W0g[NH + t] : 0.f;
        if (t < 16) S.b2s[t] = (t < out_valid) ? b2g[t] : 0.f;
    }
    __syncthreads();

    const int a_r = (lane & 7) + ((lane & 8) ? 8 : 0);
    const int a_c = (lane & 16) ? 8 : 0;
    const uint32_t h0base = (uint32_t)__cvta_generic_to_shared(&S.h0[0][0]);

    const int tile = blockIdx.x;
    {
        const int row0 = tile * 64;
        if (t < 64) {
            int rg = row0 + t;
            float xj, xi;
            if (sgrid_mode) {
                int gA = rg / GN;
                xj = (float)gA * (1.f / (float)GC);
                xi = (float)(rg - gA * GN) * (1.f / (float)GC);
            } else { xj = (float)rg * (1.f / (float)BGC); xi = 0.f; }
            S.mjs[t] = xj; S.mis[t] = xi;
        }
        __syncthreads();

        {
            int r = t >> 2, cb = (t & 3) * 64;
            float xj = S.mjs[r], xi = S.mis[r];
            #pragma unroll
            for (int k = 0; k < 64; k += 2) {
                int kk = cb + k;
                float a0 = fmaf(xj, S.W0s[0][kk],   fmaf(xi, S.W0s[1][kk],   S.b0s[kk]));
                float a1 = fmaf(xj, S.W0s[0][kk+1], fmaf(xi, S.W0s[1][kk+1], S.b0s[kk+1]));
                *reinterpret_cast<uint32_t*>(&S.h0[r][kk]) =
                    pack_bf16x2(tanh_f32(a0), tanh_f32(a1));
            }
        }
        __syncthreads();

        float acc[2][8][4];
        #pragma unroll
        for (int mt = 0; mt < 2; mt++)
            #pragma unroll
            for (int nt = 0; nt < 8; nt++)
                #pragma unroll
                for (int c = 0; c < 4; c++) acc[mt][nt][c] = 0.f;

        const int rbase = mw * 32;
        #pragma unroll 4
        for (int kt = 0; kt < 16; kt++) {
            uint32_t a[2][4];
            #pragma unroll
            for (int mt = 0; mt < 2; mt++) {
                uint32_t addr = h0base +
                    (uint32_t)(((rbase + mt * 16 + a_r) * 264 + kt * 16 + a_c) * 2);
                ldsm4(a[mt], addr);
            }
            #pragma unroll
            for (int nt = 0; nt < 8; nt++) {
                int n = nw * 64 + nt * 8 + g;
                uint32_t b0 = *reinterpret_cast<const uint32_t*>(&S.W1t[n][kt * 16 + 2 * tg]);
                uint32_t b1 = *reinterpret_cast<const uint32_t*>(&S.W1t[n][kt * 16 + 2 * tg + 8]);
                mma16816(acc[0][nt], a[0][0], a[0][1], a[0][2], a[0][3], b0, b1);
                mma16816(acc[1][nt], a[1][0], a[1][1], a[1][2], a[1][3], b0, b1);
            }
        }

        uint32_t A2[2][8][2];
        #pragma unroll
        for (int nt = 0; nt < 8; nt++) {
            int c0 = nw * 64 + nt * 8 + 2 * tg;
            float bb0 = S.b1s[c0], bb1 = S.b1s[c0 + 1];
            #pragma unroll
            for (int mt = 0; mt < 2; mt++) {
                float v0 = tanh_f32(acc[mt][nt][0] + bb0);
                float v1 = tanh_f32(acc[mt][nt][1] + bb1);
                float v2 = tanh_f32(acc[mt][nt][2] + bb0);
                float v3 = tanh_f32(acc[mt][nt][3] + bb1);
                A2[mt][nt][0] = pack_bf16x2(v0, v1);
                A2[mt][nt][1] = pack_bf16x2(v2, v3);
            }
        }

        float c2[2][2][4];
        #pragma unroll
        for (int mt = 0; mt < 2; mt++)
            #pragma unroll
            for (int nb = 0; nb < 2; nb++)
                #pragma unroll
                for (int c = 0; c < 4; c++) c2[mt][nb][c] = 0.f;

        #pragma unroll
        for (int kt2 = 0; kt2 < 4; kt2++) {
            #pragma unroll
            for (int mt = 0; mt < 2; mt++) {
                uint32_t a0 = A2[mt][2 * kt2][0],     a1 = A2[mt][2 * kt2][1];
                uint32_t a2 = A2[mt][2 * kt2 + 1][0], a3 = A2[mt][2 * kt2 + 1][1];
                #pragma unroll
                for (int nb = 0; nb < 2; nb++) {
                    uint32_t b0 = *reinterpret_cast<const uint32_t*>(
                        &S.W2t[nb * 8 + g][nw * 64 + kt2 * 16 + 2 * tg]);
                    uint32_t b1 = *reinterpret_cast<const uint32_t*>(
                        &S.W2t[nb * 8 + g][nw * 64 + kt2 * 16 + 2 * tg + 8]);
                    mma16816(c2[mt][nb], a0, a1, a2, a3, b0, b1);
                }
            }
        }

        #pragma unroll
        for (int mt = 0; mt < 2; mt++)
            #pragma unroll
            for (int nb = 0; nb < 2; nb++)
                #pragma unroll
                for (int c = 0; c < 4; c++) {
                    int rr = mt * 16 + g + ((c >> 1) & 1) * 8;
                    int cc = nb * 8 + 2 * tg + (c & 1);
                    S.red[warp][rr][cc] = c2[mt][nb][c];
                }
        __syncthreads();

        {
            int r64 = t >> 2, cq = t & 3;
            int mw2 = r64 >> 5, r32 = r64 & 31;
            #pragma unroll
            for (int cc = 0; cc < 4; cc++) {
                int col = cq * 4 + cc;
                float s = S.b2s[col];
                #pragma unroll
                for (int nn = 0; nn < 4; nn++) s += S.red[nn * 2 + mw2][r32][col];
                s = tanh_f32(s);
                if (col < out_valid) {
                    int row = row0 + r64;
                    if (sgrid_mode) g_SgH[y][row][col] = __float2half(s);
                    else            g_Bgrid[y - 4][row][col] = s;
                }
            }
        }
    }
}

// -------------------- assemble: fp16 bilerp + symplectic updates -----------
__device__ __forceinline__ void loadrow9(const __half* __restrict__ p, float* f) {
    uint4 a = *reinterpret_cast<const uint4*>(p);        // halves 0..7
    uint2 b = *reinterpret_cast<const uint2*>(p + 8);    // halves 8..11
    __half h[12];
    *reinterpret_cast<uint4*>(h) = a;
    *reinterpret_cast<uint2*>(h + 8) = b;
    #pragma unroll
    for (int c = 0; c < 9; c++) f[c] = __half2float(h[c]);
}

__device__ __forceinline__ void bilerp9h(const __half* __restrict__ Gl,
    int cu, int cv, float w00, float w01, float w10, float w11, float* A)
{
    float t00[9], t01[9], t10[9], t11[9];
    loadrow9(Gl + (size_t)(cu * GN + cv) * 16, t00);
    loadrow9(Gl + (size_t)(cu * GN + cv + 1) * 16, t01);
    loadrow9(Gl + (size_t)((cu + 1) * GN + cv) * 16, t10);
    loadrow9(Gl + (size_t)((cu + 1) * GN + cv + 1) * 16, t11);
    #pragma unroll
    for (int c = 0; c < 9; c++)
        A[c] = fmaf(w00, t00[c], fmaf(w01, t01[c], fmaf(w10, t10[c], w11 * t11[c])));
}

__global__ void __launch_bounds__(256) assemble_interp(
    const float* __restrict__ q, const float* __restrict__ p,
    const float* __restrict__ m, const float* __restrict__ dtp,
    float* __restrict__ out)
{
    __shared__ float qf[48], pf[48];
    __shared__ float fr[16]; __shared__ int cl[16];
    __shared__ float frB[16]; __shared__ int clB[16];
    const int b = blockIdx.x, t = threadIdx.x;
    if (t < 48) { qf[t] = q[b * 48 + t]; pf[t] = p[b * 48 + t]; }
    if (t < 16) {
        float mv = m[b * 16 + t];
        float u = mv * (float)GC; int c = (int)u; if (c > GC - 1) c = GC - 1;
        cl[t] = c; fr[t] = u - (float)c;
        float uB = mv * (float)BGC; int cB = (int)uB; if (cB > BGC - 1) cB = BGC - 1;
        clB[t] = cB; frB[t] = uB - (float)cB;
    }
    float dt = dtp[0];
    const float scale = dt * dt * dt;
    __syncthreads();

    const int i = t >> 4, j = t & 15;
    // orientation 1: S(i,j) = MLP(m_j, m_i); orientation 2: S(j,i) = MLP(m_i, m_j)
    const int cu1 = cl[j], cv1 = cl[i];
    const float fu1 = fr[j], fv1 = fr[i];
    const float w00_1 = (1.f - fu1) * (1.f - fv1), w01_1 = (1.f - fu1) * fv1;
    const float w10_1 = fu1 * (1.f - fv1),         w11_1 = fu1 * fv1;
    const int cu2 = cl[i], cv2 = cl[j];
    const float fu2 = fr[i], fv2 = fr[j];
    const float w00_2 = (1.f - fu2) * (1.f - fv2), w01_2 = (1.f - fu2) * fv2;
    const float w10_2 = fu2 * (1.f - fv2),         w11_2 = fu2 * fv2;

    #pragma unroll
    for (int l = 0; l < 4; l++) {
        const __half* Gl = &g_SgH[l][0][0];
        float A1[9], A2[9];
        bilerp9h(Gl, cu1, cv1, w00_1, w01_1, w10_1, w11_1, A1);
        bilerp9h(Gl, cu2, cv2, w00_2, w01_2, w10_2, w11_2, A2);
        const float* src = (l & 1) ? pf : qf;
        float*       dst = (l & 1) ? qf : pf;
        float sj0 = src[j * 3 + 0], sj1 = src[j * 3 + 1], sj2 = src[j * 3 + 2];
        float y0 = A1[0]*sj0 + A1[1]*sj1 + A1[2]*sj2
                 + A2[0]*sj0 + A2[3]*sj1 + A2[6]*sj2;
        float y1 = A1[3]*sj0 + A1[4]*sj1 + A1[5]*sj2
                 + A2[1]*sj0 + A2[4]*sj1 + A2[7]*sj2;
        float y2 = A1[6]*sj0 + A1[7]*sj1 + A1[8]*sj2
                 + A2[2]*sj0 + A2[5]*sj1 + A2[8]*sj2;
        #pragma unroll
        for (int off = 8; off; off >>= 1) {
            y0 += __shfl_xor_sync(0xffffffffu, y0, off);
            y1 += __shfl_xor_sync(0xffffffffu, y1, off);
            y2 += __shfl_xor_sync(0xffffffffu, y2, off);
        }
        if (j == 0) {
            dst[i * 3 + 0] += scale * y0;
            dst[i * 3 + 1] += scale * y1;
            dst[i * 3 + 2] += scale * y2;
        }
        __syncthreads();
    }

    if (t < 48) {
        int pi = t / 3, e = t - pi * 3;
        int c = clB[pi]; float f = frB[pi];
        float bq0 = g_Bgrid[0][c][e], bq1 = g_Bgrid[0][c + 1][e];
        float bp0 = g_Bgrid[1][c][e], bp1 = g_Bgrid[1][c + 1][e];
        out[b * 48 + t]           = qf[t] + (bq0 + f * (bq1 - bq0)) * scale;
        out[NB * 48 + b * 48 + t] = pf[t] + (bp0 + f * (bp1 - bp0)) * scale;
    }
}

// -------------------- launch ------------------------------------------------
extern "C" void kernel_launch(void* const* d_in, const int* in_sizes, int n_in,
                              void* d_out, int out_size) {
    const float* q   = (const float*)d_in[0];
    const float* p   = (const float*)d_in[1];
    const float* m   = (const float*)d_in[2];
    const float* dt  = (const float*)d_in[3];
    const float* sW0 = (const float*)d_in[4];
    const float* sb0 = (const float*)d_in[5];
    const float* sW1 = (const float*)d_in[6];
    const float* sb1 = (const float*)d_in[7];
    const float* sW2 = (const float*)d_in[8];
    const float* sb2 = (const float*)d_in[9];
    const float* qW0 = (const float*)d_in[10];
    const float* qb0 = (const float*)d_in[11];
    const float* qW1 = (const float*)d_in[12];
    const float* qb1 = (const float*)d_in[13];
    const float* qW2 = (const float*)d_in[14];
    const float* qb2 = (const float*)d_in[15];
    const float* kW0 = (const float*)d_in[16];
    const float* kb0 = (const float*)d_in[17];
    const float* kW1 = (const float*)d_in[18];
    const float* kb1 = (const float*)d_in[19];
    const float* kW2 = (const float*)d_in[20];
    const float* kb2 = (const float*)d_in[21];
    float* out = (float*)d_out;

    static bool once = false;
    if (!once) {
        cudaFuncSetAttribute(mlp_grid, cudaFuncAttributeMaxDynamicSharedMemorySize,
                             (int)sizeof(SmemLayout));
        once = true;
    }
    {
        dim3 grid(SG_TILES, 6);
        mlp_grid<<<grid, 256, sizeof(SmemLayout)>>>(
            sW0, sb0, sW1, sb1, sW2, sb2,
            qW0, qb0, qW1, qb1, qW2, qb2,
            kW0, kb0, kW1, kb1, kW2, kb2);
    }
    assemble_interp<<<NB, 256>>>(q, p, m, dt, out);
}

// round 7
// speedup vs baseline: 21.4019x; 1.1372x over previous
#include <cuda_runtime.h>
#include <cuda_bf16.h>
#include <cuda_fp16.h>
#include <stdint.h>

#define NB 1024
#define NP 16
#define NH 256
// S-grid: 25x25 nodes over [0,1]^2 -> 625 rows, padded to 640 (10 tiles of 64)
#define GN 25
#define GC 24
#define SG_TILES 10
// bias grid: 257 nodes over [0,1], padded to 320 (5 tiles)
#define BGC 256
#define BG_TILES 5

__device__ float  g_Sf[4][640][12];       // raw S MLP on grid (fp32)
__device__ __half g_Gh[625 * 48];         // symmetrized, layer-packed (96B/node)
__device__ float  g_Bgrid[2][320][4];     // bias MLPs on 1-D grid

__device__ __forceinline__ float tanh_f32(float x) {
    float y; asm("tanh.approx.f32 %0, %1;" : "=f"(y) : "f"(x)); return y;
}
__device__ __forceinline__ uint32_t pack_bf16x2(float lo, float hi) {
    uint32_t r; asm("cvt.rn.bf16x2.f32 %0, %1, %2;" : "=r"(r) : "f"(hi), "f"(lo));
    return r;
}
__device__ __forceinline__ void ldsm4(uint32_t r[4], uint32_t addr) {
    asm volatile("ldmatrix.sync.aligned.m8n8.x4.shared.b16 {%0,%1,%2,%3}, [%4];"
        : "=r"(r[0]), "=r"(r[1]), "=r"(r[2]), "=r"(r[3]) : "r"(addr));
}
__device__ __forceinline__ void mma16816(float c[4],
    uint32_t a0, uint32_t a1, uint32_t a2, uint32_t a3,
    uint32_t b0, uint32_t b1) {
    asm volatile(
        "mma.sync.aligned.m16n8k16.row.col.f32.bf16.bf16.f32 "
        "{%0,%1,%2,%3},{%4,%5,%6,%7},{%8,%9},{%0,%1,%2,%3};"
        : "+f"(c[0]), "+f"(c[1]), "+f"(c[2]), "+f"(c[3])
        : "r"(a0), "r"(a1), "r"(a2), "r"(a3), "r"(b0), "r"(b1));
}

// -------------------- MLP grid-evaluation kernel (proven core) -------------
struct __align__(16) SmemLayout {
    __nv_bfloat16 W1t[256][258];
    __nv_bfloat16 h0[64][264];
    __nv_bfloat16 W2t[16][258];
    float red[8][32][16];
    float b1s[256];
    float b0s[256];
    float W0s[2][256];
    float b2s[16];
    float mjs[64];
    float mis[64];
};

__global__ void __launch_bounds__(256, 1) mlp_grid(
    const float* __restrict__ sW0, const float* __restrict__ sb0,
    const float* __restrict__ sW1, const float* __restrict__ sb1,
    const float* __restrict__ sW2, const float* __restrict__ sb2,
    const float* __restrict__ qW0, const float* __restrict__ qb0,
    const float* __restrict__ qW1, const float* __restrict__ qb1,
    const float* __restrict__ qW2, const float* __restrict__ qb2,
    const float* __restrict__ kW0, const float* __restrict__ kb0,
    const float* __restrict__ kW1, const float* __restrict__ kb1,
    const float* __restrict__ kW2, const float* __restrict__ kb2)
{
    extern __shared__ char smem_raw[];
    SmemLayout& S = *reinterpret_cast<SmemLayout*>(smem_raw);
    const int t = threadIdx.x;
    const int warp = t >> 5, lane = t & 31;
    const int g = lane >> 2, tg = lane & 3;
    const int mw = warp & 1, nw = warp >> 1;
    const int y = blockIdx.y;
    const int sgrid_mode = (y < 4);
    const int ntiles = sgrid_mode ? SG_TILES : BG_TILES;
    if ((int)blockIdx.x >= ntiles) return;
    const int out_valid = sgrid_mode ? 9 : 3;

    const float *W0g, *b0g, *b1g, *b2g;
    const float* w1src;
    if (y < 4) { W0g = sW0 + y * 512; b0g = sb0 + y * 256; b1g = sb1 + y * 256;
                 b2g = sb2 + y * 9; w1src = sW1 + y * 65536; }
    else if (y == 4) { W0g = qW0; b0g = qb0; b1g = qb1; b2g = qb2; w1src = qW1; }
    else { W0g = kW0; b0g = kb0; b1g = kb1; b2g = kb2; w1src = kW1; }

    // ---- inline weight conversion: fp32 [k][n] -> bf16 smem [n][k] ----
    for (int it = 0; it < 256; it++)
        S.W1t[t][it] = __float2bfloat16(w1src[it * 256 + t]);
    {
        #pragma unroll
        for (int n = 0; n < 16; n++) {
            float v = 0.f;
            if (y < 4)       { if (n < 9) v = sW2[y * 2304 + t * 9 + n]; }
            else if (y == 4) { if (n < 3) v = qW2[t * 3 + n]; }
            else             { if (n < 3) v = kW2[t * 3 + n]; }
            S.W2t[n][t] = __float2bfloat16(v);
        }
        S.b1s[t] = b1g[t];
        S.b0s[t] = b0g[t];
        S.W0s[0][t] = W0g[t];
        S.W0s[1][t] = sgrid_mode ? W0g[NH + t] : 0.f;
        if (t < 16) S.b2s[t] = (t < out_valid) ? b2g[t] : 0.f;
    }
    __syncthreads();

    const int a_r = (lane & 7) + ((lane & 8) ? 8 : 0);
    const int a_c = (lane & 16) ? 8 : 0;
    const uint32_t h0base = (uint32_t)__cvta_generic_to_shared(&S.h0[0][0]);

    const int tile = blockIdx.x;
    {
        const int row0 = tile * 64;
        if (t < 64) {
            int rg = row0 + t;
            float xj, xi;
            if (sgrid_mode) {
                int gA = rg / GN;
                xj = (float)gA * (1.f / (float)GC);
                xi = (float)(rg - gA * GN) * (1.f / (float)GC);
            } else { xj = (float)rg * (1.f / (float)BGC); xi = 0.f; }
            S.mjs[t] = xj; S.mis[t] = xi;
        }
        __syncthreads();

        {
            int r = t >> 2, cb = (t & 3) * 64;
            float xj = S.mjs[r], xi = S.mis[r];
            #pragma unroll
            for (int k = 0; k < 64; k += 2) {
                int kk = cb + k;
                float a0 = fmaf(xj, S.W0s[0][kk],   fmaf(xi, S.W0s[1][kk],   S.b0s[kk]));
                float a1 = fmaf(xj, S.W0s[0][kk+1], fmaf(xi, S.W0s[1][kk+1], S.b0s[kk+1]));
                *reinterpret_cast<uint32_t*>(&S.h0[r][kk]) =
                    pack_bf16x2(tanh_f32(a0), tanh_f32(a1));
            }
        }
        __syncthreads();

        float acc[2][8][4];
        #pragma unroll
        for (int mt = 0; mt < 2; mt++)
            #pragma unroll
            for (int nt = 0; nt < 8; nt++)
                #pragma unroll
                for (int c = 0; c < 4; c++) acc[mt][nt][c] = 0.f;

        const int rbase = mw * 32;
        #pragma unroll 4
        for (int kt = 0; kt < 16; kt++) {
            uint32_t a[2][4];
            #pragma unroll
            for (int mt = 0; mt < 2; mt++) {
                uint32_t addr = h0base +
                    (uint32_t)(((rbase + mt * 16 + a_r) * 264 + kt * 16 + a_c) * 2);
                ldsm4(a[mt], addr);
            }
            #pragma unroll
            for (int nt = 0; nt < 8; nt++) {
                int n = nw * 64 + nt * 8 + g;
                uint32_t b0 = *reinterpret_cast<const uint32_t*>(&S.W1t[n][kt * 16 + 2 * tg]);
                uint32_t b1 = *reinterpret_cast<const uint32_t*>(&S.W1t[n][kt * 16 + 2 * tg + 8]);
                mma16816(acc[0][nt], a[0][0], a[0][1], a[0][2], a[0][3], b0, b1);
                mma16816(acc[1][nt], a[1][0], a[1][1], a[1][2], a[1][3], b0, b1);
            }
        }

        uint32_t A2[2][8][2];
        #pragma unroll
        for (int nt = 0; nt < 8; nt++) {
            int c0 = nw * 64 + nt * 8 + 2 * tg;
            float bb0 = S.b1s[c0], bb1 = S.b1s[c0 + 1];
            #pragma unroll
            for (int mt = 0; mt < 2; mt++) {
                float v0 = tanh_f32(acc[mt][nt][0] + bb0);
                float v1 = tanh_f32(acc[mt][nt][1] + bb1);
                float v2 = tanh_f32(acc[mt][nt][2] + bb0);
                float v3 = tanh_f32(acc[mt][nt][3] + bb1);
                A2[mt][nt][0] = pack_bf16x2(v0, v1);
                A2[mt][nt][1] = pack_bf16x2(v2, v3);
            }
        }

        float c2[2][2][4];
        #pragma unroll
        for (int mt = 0; mt < 2; mt++)
            #pragma unroll
            for (int nb = 0; nb < 2; nb++)
                #pragma unroll
                for (int c = 0; c < 4; c++) c2[mt][nb][c] = 0.f;

        #pragma unroll
        for (int kt2 = 0; kt2 < 4; kt2++) {
            #pragma unroll
            for (int mt = 0; mt < 2; mt++) {
                uint32_t a0 = A2[mt][2 * kt2][0],     a1 = A2[mt][2 * kt2][1];
                uint32_t a2 = A2[mt][2 * kt2 + 1][0], a3 = A2[mt][2 * kt2 + 1][1];
                #pragma unroll
                for (int nb = 0; nb < 2; nb++) {
                    uint32_t b0 = *reinterpret_cast<const uint32_t*>(
                        &S.W2t[nb * 8 + g][nw * 64 + kt2 * 16 + 2 * tg]);
                    uint32_t b1 = *reinterpret_cast<const uint32_t*>(
                        &S.W2t[nb * 8 + g][nw * 64 + kt2 * 16 + 2 * tg + 8]);
                    mma16816(c2[mt][nb], a0, a1, a2, a3, b0, b1);
                }
            }
        }

        #pragma unroll
        for (int mt = 0; mt < 2; mt++)
            #pragma unroll
            for (int nb = 0; nb < 2; nb++)
                #pragma unroll
                for (int c = 0; c < 4; c++) {
                    int rr = mt * 16 + g + ((c >> 1) & 1) * 8;
                    int cc = nb * 8 + 2 * tg + (c & 1);
                    S.red[warp][rr][cc] = c2[mt][nb][c];
                }
        __syncthreads();

        {
            int r64 = t >> 2, cq = t & 3;
            int mw2 = r64 >> 5, r32 = r64 & 31;
            #pragma unroll
            for (int cc = 0; cc < 4; cc++) {
                int col = cq * 4 + cc;
                float s = S.b2s[col];
                #pragma unroll
                for (int nn = 0; nn < 4; nn++) s += S.red[nn * 2 + mw2][r32][col];
                s = tanh_f32(s);
                if (col < out_valid) {
                    int row = row0 + r64;
                    if (sgrid_mode) g_Sf[y][row][col] = s;
                    else            g_Bgrid[y - 4][row][col] = s;
                }
            }
        }
    }
}

// -------------------- symmetrize + layer-pack the S table ------------------
// G_l(u,v) = S_l(u,v) + S_l(v,u)^T ; packed as [node][layer][12] halves (96B/node)
__global__ void __launch_bounds__(256) sym_kernel() {
    int idx = blockIdx.x * 256 + threadIdx.x;
    if (idx >= 625 * 4) return;
    int node = idx >> 2, l = idx & 3;
    int u = node / GN, v = node - u * GN;
    const float* Sa = &g_Sf[l][u * GN + v][0];
    const float* Sb = &g_Sf[l][v * GN + u][0];
    __half* dst = g_Gh + (size_t)node * 48 + l * 12;
    #pragma unroll
    for (int a = 0; a < 3; a++)
        #pragma unroll
        for (int c = 0; c < 3; c++)
            dst[a * 3 + c] = __float2half(Sa[a * 3 + c] + Sb[c * 3 + a]);
    dst[9] = dst[10] = dst[11] = __float2half(0.f);
}

// -------------------- assemble: single-bilerp symplectic updates -----------
__device__ __forceinline__ void acc_corner(int node, float w, float A[4][9]) {
    const uint4* p = reinterpret_cast<const uint4*>(g_Gh + (size_t)node * 48);
    uint4 d[6];
    #pragma unroll
    for (int k = 0; k < 6; k++) d[k] = __ldg(&p[k]);
    const __half* h = reinterpret_cast<const __half*>(d);
    #pragma unroll
    for (int l = 0; l < 4; l++)
        #pragma unroll
        for (int c = 0; c < 9; c++)
            A[l][c] = fmaf(w, __half2float(h[l * 12 + c]), A[l][c]);
}

__global__ void __launch_bounds__(256) assemble_interp(
    const float* __restrict__ q, const float* __restrict__ p,
    const float* __restrict__ m, const float* __restrict__ dtp,
    float* __restrict__ out)
{
    __shared__ float qf[48], pf[48];
    __shared__ float fr[16]; __shared__ int cl[16];
    __shared__ float frB[16]; __shared__ int clB[16];
    const int b = blockIdx.x, t = threadIdx.x;
    if (t < 48) { qf[t] = q[b * 48 + t]; pf[t] = p[b * 48 + t]; }
    if (t < 16) {
        float mv = m[b * 16 + t];
        float u = mv * (float)GC; int c = (int)u; if (c > GC - 1) c = GC - 1;
        cl[t] = c; fr[t] = u - (float)c;
        float uB = mv * (float)BGC; int cB = (int)uB; if (cB > BGC - 1) cB = BGC - 1;
        clB[t] = cB; frB[t] = uB - (float)cB;
    }
    float dt = dtp[0];
    const float scale = dt * dt * dt;
    __syncthreads();

    const int i = t >> 4, j = t & 15;
    // effective M_ij = bilerp of G at (x=m_j, y=m_i)
    const int cu = cl[j], cv = cl[i];
    const float fu = fr[j], fv = fr[i];
    const float w00 = (1.f - fu) * (1.f - fv), w01 = (1.f - fu) * fv;
    const float w10 = fu * (1.f - fv),         w11 = fu * fv;
    const int n00 = cu * GN + cv;

    float A[4][9];
    #pragma unroll
    for (int l = 0; l < 4; l++)
        #pragma unroll
        for (int c = 0; c < 9; c++) A[l][c] = 0.f;
    acc_corner(n00,          w00, A);
    acc_corner(n00 + 1,      w01, A);
    acc_corner(n00 + GN,     w10, A);
    acc_corner(n00 + GN + 1, w11, A);

    #pragma unroll
    for (int l = 0; l < 4; l++) {
        const float* src = (l & 1) ? pf : qf;
        float*       dst = (l & 1) ? qf : pf;
        float sj0 = src[j * 3 + 0], sj1 = src[j * 3 + 1], sj2 = src[j * 3 + 2];
        float y0 = A[l][0] * sj0 + A[l][1] * sj1 + A[l][2] * sj2;
        float y1 = A[l][3] * sj0 + A[l][4] * sj1 + A[l][5] * sj2;
        float y2 = A[l][6] * sj0 + A[l][7] * sj1 + A[l][8] * sj2;
        #pragma unroll
        for (int off = 8; off; off >>= 1) {
            y0 += __shfl_xor_sync(0xffffffffu, y0, off);
            y1 += __shfl_xor_sync(0xffffffffu, y1, off);
            y2 += __shfl_xor_sync(0xffffffffu, y2, off);
        }
        if (j == 0) {
            dst[i * 3 + 0] += scale * y0;
            dst[i * 3 + 1] += scale * y1;
            dst[i * 3 + 2] += scale * y2;
        }
        __syncthreads();
    }

    if (t < 48) {
        int pi = t / 3, e = t - pi * 3;
        int c = clB[pi]; float f = frB[pi];
        float bq0 = g_Bgrid[0][c][e], bq1 = g_Bgrid[0][c + 1][e];
        float bp0 = g_Bgrid[1][c][e], bp1 = g_Bgrid[1][c + 1][e];
        out[b * 48 + t]           = qf[t] + (bq0 + f * (bq1 - bq0)) * scale;
        out[NB * 48 + b * 48 + t] = pf[t] + (bp0 + f * (bp1 - bp0)) * scale;
    }
}

// -------------------- launch ------------------------------------------------
extern "C" void kernel_launch(void* const* d_in, const int* in_sizes, int n_in,
                              void* d_out, int out_size) {
    const float* q   = (const float*)d_in[0];
    const float* p   = (const float*)d_in[1];
    const float* m   = (const float*)d_in[2];
    const float* dt  = (const float*)d_in[3];
    const float* sW0 = (const float*)d_in[4];
    const float* sb0 = (const float*)d_in[5];
    const float* sW1 = (const float*)d_in[6];
    const float* sb1 = (const float*)d_in[7];
    const float* sW2 = (const float*)d_in[8];
    const float* sb2 = (const float*)d_in[9];
    const float* qW0 = (const float*)d_in[10];
    const float* qb0 = (const float*)d_in[11];
    const float* qW1 = (const float*)d_in[12];
    const float* qb1 = (const float*)d_in[13];
    const float* qW2 = (const float*)d_in[14];
    const float* qb2 = (const float*)d_in[15];
    const float* kW0 = (const float*)d_in[16];
    const float* kb0 = (const float*)d_in[17];
    const float* kW1 = (const float*)d_in[18];
    const float* kb1 = (const float*)d_in[19];
    const float* kW2 = (const float*)d_in[20];
    const float* kb2 = (const float*)d_in[21];
    float* out = (float*)d_out;

    static bool once = false;
    if (!once) {
        cudaFuncSetAttribute(mlp_grid, cudaFuncAttributeMaxDynamicSharedMemorySize,
                             (int)sizeof(SmemLayout));
        once = true;
    }
    {
        dim3 grid(SG_TILES, 6);
        mlp_grid<<<grid, 256, sizeof(SmemLayout)>>>(
            sW0, sb0, sW1, sb1, sW2, sb2,
            qW0, qb0, qW1, qb1, qW2, qb2,
            kW0, kb0, kW1, kb1, kW2, kb2);
    }
    sym_kernel<<<10, 256>>>();
    assemble_interp<<<NB, 256>>>(q, p, m, dt, out);
}